// round 3
// baseline (speedup 1.0000x reference)
#include <cuda_runtime.h>
#include <math.h>

#define Bv 16
#define Tv 256
#define Hv 512
#define Vv 32
#define NBLK 128
#define NTHR 256
#define XP 1540           // xq pitch in floats (385 float4)
#define SMEM_FLOATS (16*XP + 256 + 512 + 512 + 32 + 2)

__device__ float g_Kproj[Bv*Tv*Hv];
__device__ float g_qp[Bv*Hv];
__device__ float g_scores[Bv*Tv];
__device__ float g_ctx[2][Bv*Hv];
__device__ float g_h[2][2][Bv*Hv];   // [layer][parity][b*H+h]
__device__ unsigned g_bar;
__device__ unsigned g_sub[Bv];

__device__ __forceinline__ unsigned ld_acq(const unsigned* p){
    unsigned v; asm volatile("ld.acquire.gpu.u32 %0,[%1];":"=r"(v):"l"(p):"memory"); return v;
}
__device__ __forceinline__ float warp_sum(float v){
#pragma unroll
    for(int o=16;o>0;o>>=1) v += __shfl_xor_sync(0xffffffffu,v,o);
    return v;
}
__device__ __forceinline__ float warp_max(float v){
#pragma unroll
    for(int o=16;o>0;o>>=1) v = fmaxf(v,__shfl_xor_sync(0xffffffffu,v,o));
    return v;
}
__device__ __forceinline__ float sigf(float x){ return 1.0f/(1.0f+expf(-x)); }

__device__ __forceinline__ void grid_barrier(unsigned k){
    __threadfence(); __syncthreads();
    if(threadIdx.x==0){
        atomicAdd(&g_bar,1u);
        unsigned tgt = k*(unsigned)NBLK;
        while(ld_acq(&g_bar)<tgt) __nanosleep(32);
    }
    __syncthreads();
}

// ---------- Kproj = enc @ Wk^T + bk : [4096,512] ----------
__global__ void kproj_kernel(const float* __restrict__ enc, const float* __restrict__ Wk,
                             const float* __restrict__ bk){
    __shared__ float As[16][65], Bs[16][65];
    const int bm = blockIdx.x*64, bn = blockIdx.y*64, tid = threadIdx.x;
    const int tm = (tid/16)*4, tn = (tid%16)*4;
    float acc[4][4] = {};
    for(int k0=0;k0<Hv;k0+=16){
        for(int i=tid;i<64*16;i+=NTHR){
            int m=i>>4,k=i&15;
            As[k][m]=enc[(size_t)(bm+m)*Hv+k0+k];
            Bs[k][m]=Wk [(size_t)(bn+m)*Hv+k0+k];
        }
        __syncthreads();
#pragma unroll
        for(int k=0;k<16;k++){
            float a[4],b[4];
#pragma unroll
            for(int x=0;x<4;x++){ a[x]=As[k][tm+x]; b[x]=Bs[k][tn+x]; }
#pragma unroll
            for(int x=0;x<4;x++)
#pragma unroll
                for(int y=0;y<4;y++) acc[x][y]+=a[x]*b[y];
        }
        __syncthreads();
    }
#pragma unroll
    for(int x=0;x<4;x++)
#pragma unroll
        for(int y=0;y<4;y++)
            g_Kproj[(size_t)(bm+tm+x)*Hv+bn+tn+y]=acc[x][y]+bk[bn+tn+y];
}

// ---------- init: states, counters, initial qp ----------
__global__ void decoder_init(const float* __restrict__ h0in,
                             const float* __restrict__ Wq, const float* __restrict__ bq){
    const int tid=threadIdx.x, blk=blockIdx.x, gid=blk*NTHR+tid;
    if(gid<Bv*Hv){
        g_h[0][0][gid]=h0in[gid];
        g_h[1][0][gid]=h0in[Bv*Hv+gid];
        g_ctx[0][gid]=0.f; g_ctx[1][gid]=0.f;
    }
    if(gid==0) g_bar=0u;
    if(gid<Bv) g_sub[gid]=0u;
    const int ab=blk>>3, sub=blk&7, wid=tid>>5, lane=tid&31;
    const float4* h14=(const float4*)(h0in+Bv*Hv+ab*Hv);
#pragma unroll
    for(int r=0;r<8;r++){
        const int hrow=sub*64+r*8+wid;
        const float4* wr=(const float4*)(Wq+(size_t)hrow*Hv);
        float acc=0.f;
#pragma unroll
        for(int i=0;i<4;i++){
            float4 w4=wr[i*32+lane], x4=h14[i*32+lane];
            acc+=w4.x*x4.x+w4.y*x4.y+w4.z*x4.z+w4.w*x4.w;
        }
        acc=warp_sum(acc);
        if(lane==0) g_qp[ab*Hv+hrow]=acc+bq[hrow];
    }
}

// ---------- persistent decoder ----------
__global__ void __launch_bounds__(NTHR,1)
decoder_main(const float* __restrict__ enc, const float* __restrict__ c0in,
             const float* __restrict__ Wq, const float* __restrict__ bq,
             const float* __restrict__ v,  const float* __restrict__ vb,
             const float* __restrict__ Wih0, const float* __restrict__ bih0,
             const float* __restrict__ Whh0, const float* __restrict__ bhh0,
             const float* __restrict__ Wih1, const float* __restrict__ bih1,
             const float* __restrict__ Whh1, const float* __restrict__ bhh1,
             const float* __restrict__ Wout, const float* __restrict__ bout,
             float* __restrict__ out){
    extern __shared__ float sm[];
    float* xq  = sm;
    float* sg  = sm+16*XP;
    float* sq  = sg+256;
    float* sv  = sq+512;
    float* sw  = sv+512;
    float* sst = sw+32;

    const int tid=threadIdx.x, blk=blockIdx.x;
    const int wid=tid>>5, lane=tid&31;
    const int ab=blk>>3, sub=blk&7, t0=sub*32;
    unsigned bar_k=1, sub_k=1;

    sv[tid]=v[tid]; sv[tid+256]=v[tid+256];
    const float vb0=vb[0];

    // per-thread cell state (tid<64 owns (unit=blk*4+ul, batch b_))
    const int ul64=tid>>4, b64=tid&15, unit64=blk*4+ul64;
    float c0r=0.f, c1r=0.f;
    if(tid<64){
        c0r=c0in[b64*Hv+unit64];
        c1r=c0in[Bv*Hv+b64*Hv+unit64];
    }

    for(int s=0;s<Tv;s++){
        const int p=s&1, pn=p^1;

        // ---- P1: attention scores for (ab, t0..t0+31) ----
        sq[tid]=g_qp[ab*Hv+tid]; sq[tid+256]=g_qp[ab*Hv+256+tid];
        __syncthreads();
        {
            const float4* sq4=(const float4*)sq;
            const float4* sv4=(const float4*)sv;
#pragma unroll
            for(int r=0;r<4;r++){
                const int t_=t0+r*8+wid;
                const float4* kp4=(const float4*)(g_Kproj+(size_t)(ab*Tv+t_)*Hv);
                float acc=0.f;
#pragma unroll
                for(int i=0;i<4;i++){
                    float4 k4=kp4[i*32+lane], q4=sq4[i*32+lane], vv=sv4[i*32+lane];
                    acc+=vv.x*tanhf(q4.x+k4.x)+vv.y*tanhf(q4.y+k4.y)
                        +vv.z*tanhf(q4.z+k4.z)+vv.w*tanhf(q4.w+k4.w);
                }
                acc=warp_sum(acc);
                if(lane==0) g_scores[ab*Tv+t_]=acc+vb0;
            }
        }
        __threadfence(); __syncthreads();
        if(tid==0){
            atomicAdd(&g_sub[ab],1u);
            unsigned tgt=8u*sub_k;
            while(ld_acq(&g_sub[ab])<tgt) __nanosleep(32);
        }
        sub_k++; __syncthreads();

        // ---- P2: softmax stats + partial ctx ----
        if(wid==0){
            float scv[8], m=-1e30f;
#pragma unroll
            for(int j=0;j<8;j++){ scv[j]=g_scores[ab*Tv+lane+j*32]; m=fmaxf(m,scv[j]); }
            m=warp_max(m);
            float su=0.f;
#pragma unroll
            for(int j=0;j<8;j++) su+=expf(scv[j]-m);
            su=warp_sum(su);
            if(lane==0){ sst[0]=m; sst[1]=su; }
        }
        if(tid<64) g_ctx[pn][blk*64+tid]=0.f;     // pre-zero next step's ctx
        __syncthreads();
        if(tid<32) sw[tid]=expf(g_scores[ab*Tv+t0+tid]-sst[0])/sst[1];
        __syncthreads();
        {
            const int h2=tid*2;
            float a0=0.f,a1=0.f;
#pragma unroll 8
            for(int j=0;j<32;j++){
                const float wj=sw[j];
                const float2 e2=*(const float2*)(enc+(size_t)(ab*Tv+t0+j)*Hv+h2);
                a0+=wj*e2.x; a1+=wj*e2.y;
            }
            atomicAdd(&g_ctx[p][ab*Hv+h2],a0);
            atomicAdd(&g_ctx[p][ab*Hv+h2+1],a1);
        }
        grid_barrier(bar_k); bar_k++;

        // ---- P3: LSTM layer 0 ----
        for(int b_=0;b_<Bv;b_++)
            for(int k=tid;k<1536;k+=NTHR){
                float val = (k<512)? enc[(size_t)(b_*Tv+s)*Hv+k]
                          : (k<1024)? g_ctx[p][b_*Hv+k-512]
                          : g_h[0][p][b_*Hv+k-1024];
                xq[b_*XP+k]=val;
            }
        __syncthreads();
        {
            const int ul=tid>>6, gate=(tid>>4)&3, b_=tid&15;
            const int row=gate*Hv+blk*4+ul;
            const float4* wa=(const float4*)(Wih0+(size_t)row*1024);
            const float4* wb=(const float4*)(Whh0+(size_t)row*512);
            const float4* x4=(const float4*)xq + b_*(XP/4);
            float a0=bih0[row]+bhh0[row], a1=0.f;
#pragma unroll 8
            for(int k4=0;k4<256;k4++){
                float4 w=wa[k4], x=x4[k4];
                a0+=w.x*x.x+w.z*x.z; a1+=w.y*x.y+w.w*x.w;
            }
#pragma unroll 8
            for(int k4=0;k4<128;k4++){
                float4 w=wb[k4], x=x4[256+k4];
                a0+=w.x*x.x+w.z*x.z; a1+=w.y*x.y+w.w*x.w;
            }
            sg[tid]=a0+a1;
        }
        __syncthreads();
        if(tid<64){
            const float gi=sg[ul64*64+b64], gf=sg[ul64*64+16+b64];
            const float gg=sg[ul64*64+32+b64], go=sg[ul64*64+48+b64];
            c0r=sigf(gf)*c0r+sigf(gi)*tanhf(gg);
            g_h[0][pn][b64*Hv+unit64]=sigf(go)*tanhf(c0r);
        }
        grid_barrier(bar_k); bar_k++;

        // ---- P4: LSTM layer 1 ----
        for(int b_=0;b_<Bv;b_++)
            for(int k=tid;k<1024;k+=NTHR){
                float val=(k<512)? g_h[0][pn][b_*Hv+k] : g_h[1][p][b_*Hv+k-512];
                xq[b_*XP+k]=val;
            }
        __syncthreads();
        {
            const int ul=tid>>6, gate=(tid>>4)&3, b_=tid&15;
            const int row=gate*Hv+blk*4+ul;
            const float4* wa=(const float4*)(Wih1+(size_t)row*512);
            const float4* wb=(const float4*)(Whh1+(size_t)row*512);
            const float4* x4=(const float4*)xq + b_*(XP/4);
            float a0=bih1[row]+bhh1[row], a1=0.f;
#pragma unroll 8
            for(int k4=0;k4<128;k4++){
                float4 w=wa[k4], x=x4[k4];
                a0+=w.x*x.x+w.z*x.z; a1+=w.y*x.y+w.w*x.w;
            }
#pragma unroll 8
            for(int k4=0;k4<128;k4++){
                float4 w=wb[k4], x=x4[128+k4];
                a0+=w.x*x.x+w.z*x.z; a1+=w.y*x.y+w.w*x.w;
            }
            sg[tid]=a0+a1;
        }
        __syncthreads();
        if(tid<64){
            const float gi=sg[ul64*64+b64], gf=sg[ul64*64+16+b64];
            const float gg=sg[ul64*64+32+b64], go=sg[ul64*64+48+b64];
            c1r=sigf(gf)*c1r+sigf(gi)*tanhf(gg);
            g_h[1][pn][b64*Hv+unit64]=sigf(go)*tanhf(c1r);
        }
        grid_barrier(bar_k); bar_k++;

        // ---- P5: qp (next step) + logits ----
        {
            const float* h1n=g_h[1][pn];
#pragma unroll
            for(int j=0;j<8;j++){
                const int r=blk*64+wid*8+j, b=r>>9, h=r&511;
                const float4* wq4=(const float4*)(Wq+(size_t)h*Hv);
                const float4* hb4=(const float4*)(h1n+b*Hv);
                float acc=0.f;
#pragma unroll
                for(int i=0;i<4;i++){
                    float4 w4=wq4[i*32+lane], x4=hb4[i*32+lane];
                    acc+=w4.x*x4.x+w4.y*x4.y+w4.z*x4.z+w4.w*x4.w;
                }
                acc=warp_sum(acc);
                if(lane==0) g_qp[b*Hv+h]=acc+bq[h];
            }
            if(wid<4){
                const int lr=blk*4+wid, b=lr>>5, vo=lr&31;
                const float4* wo4=(const float4*)(Wout+(size_t)vo*Hv);
                const float4* hb4=(const float4*)(h1n+b*Hv);
                float acc=0.f;
#pragma unroll
                for(int i=0;i<4;i++){
                    float4 w4=wo4[i*32+lane], x4=hb4[i*32+lane];
                    acc+=w4.x*x4.x+w4.y*x4.y+w4.z*x4.z+w4.w*x4.w;
                }
                acc=warp_sum(acc);
                if(lane==0) out[(size_t)(b*Tv+s)*Vv+vo]=acc+bout[vo];
            }
        }
        grid_barrier(bar_k); bar_k++;
    }
}

extern "C" void kernel_launch(void* const* d_in, const int* in_sizes, int n_in,
                              void* d_out, int out_size){
    const float* enc  =(const float*)d_in[0];
    const float* h0in =(const float*)d_in[1];
    const float* c0in =(const float*)d_in[2];
    const float* Wq   =(const float*)d_in[4];
    const float* bq   =(const float*)d_in[5];
    const float* Wk   =(const float*)d_in[6];
    const float* bk   =(const float*)d_in[7];
    const float* v    =(const float*)d_in[8];
    const float* vb   =(const float*)d_in[9];
    const float* Wih0 =(const float*)d_in[10];
    const float* bih0 =(const float*)d_in[11];
    const float* Whh0 =(const float*)d_in[12];
    const float* bhh0 =(const float*)d_in[13];
    const float* Wih1 =(const float*)d_in[14];
    const float* bih1 =(const float*)d_in[15];
    const float* Whh1 =(const float*)d_in[16];
    const float* bhh1 =(const float*)d_in[17];
    const float* Wout =(const float*)d_in[18];
    const float* bout =(const float*)d_in[19];
    float* out=(float*)d_out;

    const int smem_bytes = SMEM_FLOATS*4;
    cudaFuncSetAttribute(decoder_main, cudaFuncAttributeMaxDynamicSharedMemorySize, smem_bytes);

    kproj_kernel<<<dim3(64,8),NTHR>>>(enc,Wk,bk);
    decoder_init<<<NBLK,NTHR>>>(h0in,Wq,bq);
    decoder_main<<<NBLK,NTHR,smem_bytes>>>(enc,c0in,Wq,bq,v,vb,
        Wih0,bih0,Whh0,bhh0,Wih1,bih1,Whh1,bhh1,Wout,bout,out);
}

// round 4
// speedup vs baseline: 2.2257x; 2.2257x over previous
#include <cuda_runtime.h>
#include <math.h>

#define Bv 16
#define Tv 256
#define Hv 512
#define Vv 32
#define NBLK 128
#define NTHR 256

// smem layout (floats)
// P3 xq: 16 rows, row pitch 401 float4 (1604 f), chunk pitch 25 f4 (K=1536, 16 chunks of 96)
// P4 xq: row pitch 273 f4 (1092 f), chunk pitch 17 f4 (K=1024, 16 chunks of 64)
#define SM_XQ   0
#define SM_RED  25664            // 16*1604
#define SM_SG   (25664+4096)
#define SM_SQ   (SM_SG+256)
#define SM_SV   (SM_SQ+512)
#define SM_SW   (SM_SV+512)
#define SM_SST  (SM_SW+32)
#define SMEM_FLOATS (SM_SST+2)

__device__ float g_W0[2048*1536];     // [Wih0 | Whh0] rows
__device__ float g_W1[2048*1024];     // [Wih1 | Whh1] rows
__device__ float g_Kproj[Bv*Tv*Hv];
__device__ float g_qp[Bv*Hv];
__device__ float g_scores[Bv*Tv];
__device__ float g_ctx[2][Bv*Hv];
__device__ float g_h[2][2][Bv*Hv];    // [layer][parity][b*H+h]
__device__ unsigned g_bar;
__device__ unsigned g_sub[Bv];

__device__ __forceinline__ unsigned ld_acq(const unsigned* p){
    unsigned v; asm volatile("ld.acquire.gpu.u32 %0,[%1];":"=r"(v):"l"(p):"memory"); return v;
}
__device__ __forceinline__ float warp_sum(float v){
#pragma unroll
    for(int o=16;o>0;o>>=1) v += __shfl_xor_sync(0xffffffffu,v,o);
    return v;
}
__device__ __forceinline__ float warp_max(float v){
#pragma unroll
    for(int o=16;o>0;o>>=1) v = fmaxf(v,__shfl_xor_sync(0xffffffffu,v,o));
    return v;
}
__device__ __forceinline__ float sigf(float x){ return 1.0f/(1.0f+expf(-x)); }

__device__ __forceinline__ void grid_barrier(unsigned k){
    __threadfence(); __syncthreads();
    if(threadIdx.x==0){
        atomicAdd(&g_bar,1u);
        unsigned tgt = k*(unsigned)NBLK;
        while(ld_acq(&g_bar)<tgt) __nanosleep(32);
    }
    __syncthreads();
}

// ---------- one-time: concatenate LSTM weights ----------
__global__ void wcat_kernel(const float* __restrict__ Wih0, const float* __restrict__ Whh0,
                            const float* __restrict__ Wih1, const float* __restrict__ Whh1){
    const int row = blockIdx.x;   // 2048
    const int tid = threadIdx.x;  // 128
    const float4* a0 = (const float4*)(Wih0 + (size_t)row*1024);
    const float4* b0 = (const float4*)(Whh0 + (size_t)row*512);
    float4* d0 = (float4*)(g_W0 + (size_t)row*1536);
#pragma unroll
    for(int i=0;i<2;i++) d0[tid+i*128] = a0[tid+i*128];
    d0[256+tid] = b0[tid];
    const float4* a1 = (const float4*)(Wih1 + (size_t)row*512);
    const float4* b1 = (const float4*)(Whh1 + (size_t)row*512);
    float4* d1 = (float4*)(g_W1 + (size_t)row*1024);
    d1[tid]     = a1[tid];
    d1[128+tid] = b1[tid];
}

// ---------- Kproj = enc @ Wk^T + bk : [4096,512] ----------
__global__ void kproj_kernel(const float* __restrict__ enc, const float* __restrict__ Wk,
                             const float* __restrict__ bk){
    __shared__ float As[16][65], Bs[16][65];
    const int bm = blockIdx.x*64, bn = blockIdx.y*64, tid = threadIdx.x;
    const int tm = (tid/16)*4, tn = (tid%16)*4;
    float acc[4][4] = {};
    for(int k0=0;k0<Hv;k0+=16){
        for(int i=tid;i<64*16;i+=NTHR){
            int m=i>>4,k=i&15;
            As[k][m]=enc[(size_t)(bm+m)*Hv+k0+k];
            Bs[k][m]=Wk [(size_t)(bn+m)*Hv+k0+k];
        }
        __syncthreads();
#pragma unroll
        for(int k=0;k<16;k++){
            float a[4],b[4];
#pragma unroll
            for(int x=0;x<4;x++){ a[x]=As[k][tm+x]; b[x]=Bs[k][tn+x]; }
#pragma unroll
            for(int x=0;x<4;x++)
#pragma unroll
                for(int y=0;y<4;y++) acc[x][y]+=a[x]*b[y];
        }
        __syncthreads();
    }
#pragma unroll
    for(int x=0;x<4;x++)
#pragma unroll
        for(int y=0;y<4;y++)
            g_Kproj[(size_t)(bm+tm+x)*Hv+bn+tn+y]=acc[x][y]+bk[bn+tn+y];
}

// ---------- init: states, counters, initial qp ----------
__global__ void decoder_init(const float* __restrict__ h0in,
                             const float* __restrict__ Wq, const float* __restrict__ bq){
    const int tid=threadIdx.x, blk=blockIdx.x, gid=blk*NTHR+tid;
    if(gid<Bv*Hv){
        g_h[0][0][gid]=h0in[gid];
        g_h[1][0][gid]=h0in[Bv*Hv+gid];
        g_ctx[0][gid]=0.f; g_ctx[1][gid]=0.f;
    }
    if(gid==0) g_bar=0u;
    if(gid<Bv) g_sub[gid]=0u;
    const int ab=blk>>3, sub=blk&7, wid=tid>>5, lane=tid&31;
    const float4* h14=(const float4*)(h0in+Bv*Hv+ab*Hv);
#pragma unroll
    for(int r=0;r<8;r++){
        const int hrow=sub*64+r*8+wid;
        const float4* wr=(const float4*)(Wq+(size_t)hrow*Hv);
        float acc=0.f;
#pragma unroll
        for(int i=0;i<4;i++){
            float4 w4=wr[i*32+lane], x4=h14[i*32+lane];
            acc+=w4.x*x4.x+w4.y*x4.y+w4.z*x4.z+w4.w*x4.w;
        }
        acc=warp_sum(acc);
        if(lane==0) g_qp[ab*Hv+hrow]=acc+bq[hrow];
    }
}

// ---------- persistent decoder ----------
__global__ void __launch_bounds__(NTHR,1)
decoder_main(const float* __restrict__ enc, const float* __restrict__ c0in,
             const float* __restrict__ Wq, const float* __restrict__ bq,
             const float* __restrict__ v,  const float* __restrict__ vb,
             const float* __restrict__ bih0, const float* __restrict__ bhh0,
             const float* __restrict__ bih1, const float* __restrict__ bhh1,
             const float* __restrict__ Wout, const float* __restrict__ bout,
             float* __restrict__ out){
    extern __shared__ float sm[];
    float4* xq4 = (float4*)(sm + SM_XQ);

    const int tid=threadIdx.x, blk=blockIdx.x;
    const int wid=tid>>5, lane=tid&31;
    const int ab=blk>>3, sub=blk&7, t0=sub*32;
    unsigned bar_k=1, sub_k=1;

    sm[SM_SV+tid]=v[tid]; sm[SM_SV+tid+256]=v[tid+256];
    const float vb0=vb[0];

    // gemv thread coords: 2 kc x 4 rg x 4 bg per warp
    const int kc = tid>>4, rg = (tid>>2)&3, bg = tid&3;
    // cell-update ownership (tid<64): unit=blk*4+ul64, batch b64
    const int ul64=tid>>4, b64=tid&15, unit64=blk*4+ul64;
    float c0r=0.f, c1r=0.f;
    if(tid<64){
        c0r=c0in[b64*Hv+unit64];
        c1r=c0in[Bv*Hv+b64*Hv+unit64];
    }

    for(int s=0;s<Tv;s++){
        const int p=s&1, pn=p^1;

        // ======== P1: attention scores for (ab, t0..t0+31) ========
        sm[SM_SQ+tid]=g_qp[ab*Hv+tid]; sm[SM_SQ+tid+256]=g_qp[ab*Hv+256+tid];
        __syncthreads();
        {
            const float4* sq4=(const float4*)(sm+SM_SQ);
            const float4* sv4=(const float4*)(sm+SM_SV);
#pragma unroll
            for(int r=0;r<4;r++){
                const int t_=t0+r*8+wid;
                const float4* kp4=(const float4*)(g_Kproj+(size_t)(ab*Tv+t_)*Hv);
                float acc=0.f;
#pragma unroll
                for(int i=0;i<4;i++){
                    float4 k4=kp4[i*32+lane], q4=sq4[i*32+lane], vv=sv4[i*32+lane];
                    acc+=vv.x*tanhf(q4.x+k4.x)+vv.y*tanhf(q4.y+k4.y)
                        +vv.z*tanhf(q4.z+k4.z)+vv.w*tanhf(q4.w+k4.w);
                }
                acc=warp_sum(acc);
                if(lane==0) g_scores[ab*Tv+t_]=acc+vb0;
            }
        }
        __threadfence(); __syncthreads();
        if(tid==0){
            atomicAdd(&g_sub[ab],1u);
            unsigned tgt=8u*sub_k;
            while(ld_acq(&g_sub[ab])<tgt) __nanosleep(32);
        }
        sub_k++; __syncthreads();

        // ======== P2: softmax stats + partial ctx ========
        if(wid==0){
            float scv[8], m=-1e30f;
#pragma unroll
            for(int j=0;j<8;j++){ scv[j]=g_scores[ab*Tv+lane+j*32]; m=fmaxf(m,scv[j]); }
            m=warp_max(m);
            float su=0.f;
#pragma unroll
            for(int j=0;j<8;j++) su+=expf(scv[j]-m);
            su=warp_sum(su);
            if(lane==0){ sm[SM_SST]=m; sm[SM_SST+1]=su; }
        }
        if(tid<64) g_ctx[pn][blk*64+tid]=0.f;   // pre-zero next parity's ctx
        __syncthreads();
        if(tid<32) sm[SM_SW+tid]=expf(g_scores[ab*Tv+t0+tid]-sm[SM_SST])/sm[SM_SST+1];
        __syncthreads();
        {
            const int h2=tid*2;
            float a0=0.f,a1=0.f;
#pragma unroll 8
            for(int j=0;j<32;j++){
                const float wj=sm[SM_SW+j];
                const float2 e2=*(const float2*)(enc+(size_t)(ab*Tv+t0+j)*Hv+h2);
                a0+=wj*e2.x; a1+=wj*e2.y;
            }
            atomicAdd(&g_ctx[p][ab*Hv+h2],a0);
            atomicAdd(&g_ctx[p][ab*Hv+h2+1],a1);
        }
        grid_barrier(bar_k); bar_k++;

        // ======== P3: LSTM layer 0 (rows gate*512+blk*4+ul), K=1536 ========
        {   // stage x = [enc_t | ctx | h0_old], chunked layout
            const float* h0p = g_h[0][p];
            const float* ctx = g_ctx[p];
            for(int idx=tid; idx<16*384; idx+=NTHR){
                const int b_=idx/384, k4g=idx-b_*384;
                float4 val;
                if(k4g<128)      val=*(const float4*)(enc+(size_t)(b_*Tv+s)*Hv+k4g*4);
                else if(k4g<256) val=*(const float4*)(ctx+b_*Hv+(k4g-128)*4);
                else             val=*(const float4*)(h0p+b_*Hv+(k4g-256)*4);
                const int kcs=k4g/24, k4=k4g-kcs*24;
                xq4[b_*401+kcs*25+k4]=val;
            }
        }
        __syncthreads();
        {
            const float4* wb=(const float4*)g_W0 + (size_t)(rg*512+blk*4)*384 + kc*24;
            const float4* xb=xq4 + (bg*4)*401 + kc*25;
            float acc[4][4]={};
#pragma unroll 4
            for(int k4=0;k4<24;k4++){
                float4 xv[4], wv[4];
#pragma unroll
                for(int j=0;j<4;j++) xv[j]=xb[j*401+k4];
#pragma unroll
                for(int i=0;i<4;i++) wv[i]=wb[(size_t)i*384+k4];
#pragma unroll
                for(int i=0;i<4;i++)
#pragma unroll
                    for(int j=0;j<4;j++)
                        acc[i][j]+=wv[i].x*xv[j].x+wv[i].y*xv[j].y+wv[i].z*xv[j].z+wv[i].w*xv[j].w;
            }
            float* red = sm+SM_RED+kc*256;
#pragma unroll
            for(int i=0;i<4;i++)
                *(float4*)(red+(rg*4+i)*16+bg*4)=make_float4(acc[i][0],acc[i][1],acc[i][2],acc[i][3]);
        }
        __syncthreads();
        {
            const int r16=tid>>4, b_=tid&15;
            float g=0.f;
#pragma unroll
            for(int kk=0;kk<16;kk++) g+=sm[SM_RED+kk*256+r16*16+b_];
            const int grow=(r16>>2)*512+blk*4+(r16&3);
            sm[SM_SG+tid]=g+bih0[grow]+bhh0[grow];
        }
        __syncthreads();
        if(tid<64){
            const float gi=sm[SM_SG+(0+ul64)*16+b64], gf=sm[SM_SG+(4+ul64)*16+b64];
            const float gg=sm[SM_SG+(8+ul64)*16+b64], go=sm[SM_SG+(12+ul64)*16+b64];
            c0r=sigf(gf)*c0r+sigf(gi)*tanhf(gg);
            g_h[0][pn][b64*Hv+unit64]=sigf(go)*tanhf(c0r);
        }
        grid_barrier(bar_k); bar_k++;

        // ======== P4: LSTM layer 1, K=1024 ========
        {   // stage x = [h0_new | h1_old]
            const float4* h0n=(const float4*)g_h[0][pn];
            const float4* h1o=(const float4*)g_h[1][p];
            for(int idx=tid; idx<16*256; idx+=NTHR){
                const int b_=idx>>8, k4g=idx&255;
                float4 val=(k4g<128)? h0n[b_*128+k4g] : h1o[b_*128+(k4g-128)];
                const int kcs=k4g>>4, k4=k4g&15;
                xq4[b_*273+kcs*17+k4]=val;
            }
        }
        __syncthreads();
        {
            const float4* wb=(const float4*)g_W1 + (size_t)(rg*512+blk*4)*256 + kc*16;
            const float4* xb=xq4 + (bg*4)*273 + kc*17;
            float acc[4][4]={};
#pragma unroll 4
            for(int k4=0;k4<16;k4++){
                float4 xv[4], wv[4];
#pragma unroll
                for(int j=0;j<4;j++) xv[j]=xb[j*273+k4];
#pragma unroll
                for(int i=0;i<4;i++) wv[i]=wb[(size_t)i*256+k4];
#pragma unroll
                for(int i=0;i<4;i++)
#pragma unroll
                    for(int j=0;j<4;j++)
                        acc[i][j]+=wv[i].x*xv[j].x+wv[i].y*xv[j].y+wv[i].z*xv[j].z+wv[i].w*xv[j].w;
            }
            float* red = sm+SM_RED+kc*256;
#pragma unroll
            for(int i=0;i<4;i++)
                *(float4*)(red+(rg*4+i)*16+bg*4)=make_float4(acc[i][0],acc[i][1],acc[i][2],acc[i][3]);
        }
        __syncthreads();
        {
            const int r16=tid>>4, b_=tid&15;
            float g=0.f;
#pragma unroll
            for(int kk=0;kk<16;kk++) g+=sm[SM_RED+kk*256+r16*16+b_];
            const int grow=(r16>>2)*512+blk*4+(r16&3);
            sm[SM_SG+tid]=g+bih1[grow]+bhh1[grow];
        }
        __syncthreads();
        if(tid<64){
            const float gi=sm[SM_SG+(0+ul64)*16+b64], gf=sm[SM_SG+(4+ul64)*16+b64];
            const float gg=sm[SM_SG+(8+ul64)*16+b64], go=sm[SM_SG+(12+ul64)*16+b64];
            c1r=sigf(gf)*c1r+sigf(gi)*tanhf(gg);
            g_h[1][pn][b64*Hv+unit64]=sigf(go)*tanhf(c1r);
        }
        grid_barrier(bar_k); bar_k++;

        // ======== P5: qp (next step) + logits (this block only needs batch blk>>3) ========
        {
            const int bneed=blk>>3;
            const float4* h1n4=(const float4*)g_h[1][pn];
            if(tid<128) xq4[tid]=h1n4[bneed*128+tid];
            __syncthreads();
#pragma unroll
            for(int j=0;j<8;j++){
                const int h=(blk&7)*64+wid*8+j;
                const float4* wq4=(const float4*)(Wq+(size_t)h*Hv);
                float acc=0.f;
#pragma unroll
                for(int i=0;i<4;i++){
                    float4 w4=wq4[i*32+lane], x4=xq4[i*32+lane];
                    acc+=w4.x*x4.x+w4.y*x4.y+w4.z*x4.z+w4.w*x4.w;
                }
                acc=warp_sum(acc);
                if(lane==0) g_qp[bneed*Hv+h]=acc+bq[h];
            }
            if(wid<4){
                const int vo=(blk&7)*4+wid;
                const float4* wo4=(const float4*)(Wout+(size_t)vo*Hv);
                float acc=0.f;
#pragma unroll
                for(int i=0;i<4;i++){
                    float4 w4=wo4[i*32+lane], x4=xq4[i*32+lane];
                    acc+=w4.x*x4.x+w4.y*x4.y+w4.z*x4.z+w4.w*x4.w;
                }
                acc=warp_sum(acc);
                if(lane==0) out[(size_t)(bneed*Tv+s)*Vv+vo]=acc+bout[vo];
            }
        }
        grid_barrier(bar_k); bar_k++;
    }
}

extern "C" void kernel_launch(void* const* d_in, const int* in_sizes, int n_in,
                              void* d_out, int out_size){
    const float* enc  =(const float*)d_in[0];
    const float* h0in =(const float*)d_in[1];
    const float* c0in =(const float*)d_in[2];
    const float* Wq   =(const float*)d_in[4];
    const float* bq   =(const float*)d_in[5];
    const float* Wk   =(const float*)d_in[6];
    const float* bk   =(const float*)d_in[7];
    const float* v    =(const float*)d_in[8];
    const float* vb   =(const float*)d_in[9];
    const float* Wih0 =(const float*)d_in[10];
    const float* bih0 =(const float*)d_in[11];
    const float* Whh0 =(const float*)d_in[12];
    const float* bhh0 =(const float*)d_in[13];
    const float* Wih1 =(const float*)d_in[14];
    const float* bih1 =(const float*)d_in[15];
    const float* Whh1 =(const float*)d_in[16];
    const float* bhh1 =(const float*)d_in[17];
    const float* Wout =(const float*)d_in[18];
    const float* bout =(const float*)d_in[19];
    float* out=(float*)d_out;

    const int smem_bytes = SMEM_FLOATS*4;
    cudaFuncSetAttribute(decoder_main, cudaFuncAttributeMaxDynamicSharedMemorySize, smem_bytes);

    wcat_kernel<<<2048,128>>>(Wih0,Whh0,Wih1,Whh1);
    kproj_kernel<<<dim3(64,8),NTHR>>>(enc,Wk,bk);
    decoder_init<<<NBLK,NTHR>>>(h0in,Wq,bq);
    decoder_main<<<NBLK,NTHR,smem_bytes>>>(enc,c0in,Wq,bq,v,vb,
        bih0,bhh0,bih1,bhh1,Wout,bout,out);
}